// round 17
// baseline (speedup 1.0000x reference)
#include <cuda_runtime.h>
#include <cuda_fp16.h>

#define L1D 16
#define IN_DIM 128
#define MAXN 65536
#define ZST 132      // padded smem row stride (floats)
#define NPB1 60      // nodes per block, kernel 1 (smem fits 48KB static)
#define WROW 40      // combined weight row stride in halves (32 data + 8 pad)

// Scratch: node hidden activations in fp16 (allowed: __device__ globals)
__device__ __align__(16) __half g_h1h[MAXN * L1D];
__device__ __align__(16) __half g_h2h[MAXN * L1D];

// packed f32x2 fma: d = a*b + d
__device__ __forceinline__ void fma_f32x2(unsigned long long& d,
                                          unsigned long long a,
                                          unsigned long long b) {
    asm("fma.rn.f32x2 %0, %1, %2, %0;" : "+l"(d) : "l"(a), "l"(b));
}
__device__ __forceinline__ float unpack_sum(unsigned long long v) {
    float lo = __uint_as_float((unsigned)(v & 0xFFFFFFFFu));
    float hi = __uint_as_float((unsigned)(v >> 32));
    return lo + hi;
}

// ---------------------------------------------------------------------------
// Kernel 1 (v3): per-node tiny MLP.  h1 = relu(z @ w1_l1), h2 = relu(z @ w2_l1)
// 128 threads, 60 nodes/block. Thread = (4 nodes x 2 adjacent cols): each z
// read feeds 2 output cols (z LDS per node -28%), all math fp32 f32x2 (no
// cvt overhead), adjacent-col results stored as one __half2.
// smem: 60*132*4 + 2*16*132*4 = 48576 B (<= 48KB static).
// ---------------------------------------------------------------------------
__global__ __launch_bounds__(128) void node_mlp_kernel(
    const float* __restrict__ z,
    const float* __restrict__ w1,
    const float* __restrict__ w2,
    int n_nodes)
{
    __shared__ float zs[NPB1 * ZST];     // 31680 B
    __shared__ float w1T[L1D * ZST];     // [col][k], 8448 B
    __shared__ float w2T[L1D * ZST];     // 8448 B

    const int tid = threadIdx.x;
    const int nbase = blockIdx.x * NPB1;

    // stage weights transposed to [col][k]
    for (int i = tid; i < IN_DIM * L1D; i += 128) {
        int k = i >> 4, c = i & 15;
        w1T[c * ZST + k] = w1[i];
        w2T[c * ZST + k] = w2[i];
    }
    // stage z tile (coalesced float4)
    {
        const float4* z4 = (const float4*)(z + (size_t)nbase * IN_DIM);
        int nval = n_nodes - nbase; if (nval > NPB1) nval = NPB1;
        for (int i = tid; i < nval * (IN_DIM / 4); i += 128) {
            int r = i >> 5, q = i & 31;
            *(float4*)(zs + r * ZST + q * 4) = z4[i];
        }
    }
    __syncthreads();

    const int cg = tid & 7;              // col-pair group: cols 2cg, 2cg+1
    const int ng = tid >> 3;             // node group 0..15
    const int c0 = 2 * cg, c1 = c0 + 1;
    int r0 = ng * 4;
    if (r0 > NPB1 - 4) r0 = NPB1 - 4;    // ng=15 duplicates rows 56..59 (benign)

    // acc[table][j][col], packed f32x2
    unsigned long long acc[2][4][2] = {};

    #pragma unroll 2
    for (int k = 0; k < IN_DIM; k += 8) {
        ulonglong2 wa0a = *(const ulonglong2*)(w1T + c0 * ZST + k);
        ulonglong2 wa0b = *(const ulonglong2*)(w1T + c0 * ZST + k + 4);
        ulonglong2 wa1a = *(const ulonglong2*)(w1T + c1 * ZST + k);
        ulonglong2 wa1b = *(const ulonglong2*)(w1T + c1 * ZST + k + 4);
        ulonglong2 wb0a = *(const ulonglong2*)(w2T + c0 * ZST + k);
        ulonglong2 wb0b = *(const ulonglong2*)(w2T + c0 * ZST + k + 4);
        ulonglong2 wb1a = *(const ulonglong2*)(w2T + c1 * ZST + k);
        ulonglong2 wb1b = *(const ulonglong2*)(w2T + c1 * ZST + k + 4);
        #pragma unroll
        for (int j = 0; j < 4; j++) {
            const float* zr = zs + (r0 + j) * ZST + k;
            ulonglong2 za = *(const ulonglong2*)zr;
            ulonglong2 zb = *(const ulonglong2*)(zr + 4);
            fma_f32x2(acc[0][j][0], za.x, wa0a.x);
            fma_f32x2(acc[0][j][0], za.y, wa0a.y);
            fma_f32x2(acc[0][j][0], zb.x, wa0b.x);
            fma_f32x2(acc[0][j][0], zb.y, wa0b.y);
            fma_f32x2(acc[0][j][1], za.x, wa1a.x);
            fma_f32x2(acc[0][j][1], za.y, wa1a.y);
            fma_f32x2(acc[0][j][1], zb.x, wa1b.x);
            fma_f32x2(acc[0][j][1], zb.y, wa1b.y);
            fma_f32x2(acc[1][j][0], za.x, wb0a.x);
            fma_f32x2(acc[1][j][0], za.y, wb0a.y);
            fma_f32x2(acc[1][j][0], zb.x, wb0b.x);
            fma_f32x2(acc[1][j][0], zb.y, wb0b.y);
            fma_f32x2(acc[1][j][1], za.x, wb1a.x);
            fma_f32x2(acc[1][j][1], za.y, wb1a.y);
            fma_f32x2(acc[1][j][1], zb.x, wb1b.x);
            fma_f32x2(acc[1][j][1], zb.y, wb1b.y);
        }
    }

    #pragma unroll
    for (int j = 0; j < 4; j++) {
        int node = nbase + r0 + j;
        if (node < n_nodes) {
            float v10 = fmaxf(unpack_sum(acc[0][j][0]), 0.f);
            float v11 = fmaxf(unpack_sum(acc[0][j][1]), 0.f);
            float v20 = fmaxf(unpack_sum(acc[1][j][0]), 0.f);
            float v21 = fmaxf(unpack_sum(acc[1][j][1]), 0.f);
            *(__half2*)(g_h1h + node * L1D + c0) =
                __floats2half2_rn(v10, v11);
            *(__half2*)(g_h2h + node * L1D + c0) =
                __floats2half2_rn(v20, v21);
        }
    }
}

// ---------------------------------------------------------------------------
// Kernel 2: per-edge scoring, 4 lanes per edge, consecutive edge pair per
// group-iteration; role-split vector index loads; combined fp16 weight rows;
// paired float2 store. (Measured-best version; grid bumped to 8 blocks/SM.)
// ---------------------------------------------------------------------------
__global__ __launch_bounds__(256) void edge_kernel(
    const float* __restrict__ w1_l2,
    const float* __restrict__ w2_l2,
    const void* __restrict__ ei,
    const void* __restrict__ et,
    float* __restrict__ out,
    int n_edges, int n_etype)
{
    extern __shared__ __half wch[];   // [n_etype][WROW]
    __shared__ int s_is64;

    if (threadIdx.x < 32) {
        unsigned v = ((const unsigned*)ei)[2 * threadIdx.x + 1];
        unsigned any = __ballot_sync(0xFFFFFFFFu, v != 0u);
        if (threadIdx.x == 0) s_is64 = (any == 0u) ? 1 : 0;
    }
    for (int i = threadIdx.x; i < n_etype * 4; i += blockDim.x) {
        int t = i >> 2, q = i & 3;
        const float4* src = (q < 2) ? (const float4*)w1_l2 : (const float4*)w2_l2;
        int qq = q & 1;
        float4 fa = src[t * 4 + qq * 2];
        float4 fb = src[t * 4 + qq * 2 + 1];
        __half2 h0 = __float22half2_rn(make_float2(fa.x, fa.y));
        __half2 h1 = __float22half2_rn(make_float2(fa.z, fa.w));
        __half2 h2 = __float22half2_rn(make_float2(fb.x, fb.y));
        __half2 h3 = __float22half2_rn(make_float2(fb.z, fb.w));
        uint4 pk = make_uint4(*(unsigned*)&h0, *(unsigned*)&h1,
                              *(unsigned*)&h2, *(unsigned*)&h3);
        *(uint4*)(wch + t * WROW + q * 8) = pk;
    }
    __syncthreads();

    const int is64 = s_is64;
    const bool even = (n_edges & 1) == 0;
    const int sub = threadIdx.x & 3;
    const int lane_group = (threadIdx.x >> 2) & 7;
    const int group0 = (blockIdx.x * blockDim.x + threadIdx.x) >> 2;
    const int G = (gridDim.x * blockDim.x) >> 2;
    const int warp_base0 = group0 - lane_group;
    const int npairs = (n_edges + 1) >> 1;
    const int pmax = npairs - 1;
    const int emax = n_edges - 1;

    const __half* htab = (sub < 2) ? g_h1h : g_h2h;
    const int hq = (sub & 1) * 8;
    const size_t noff = (sub < 2) ? 0 : (size_t)n_edges;

    const long long* p64 = (const long long*)ei + noff;
    const int*       p32 = (const int*)ei + noff;
    const long long* t64 = (const long long*)et;
    const int*       t32 = (const int*)et;

    for (int base = warp_base0; base < npairs; base += G) {
        int pp = base + lane_group;
        int pc = pp < npairs ? pp : pmax;
        int e0 = 2 * pc;

        int nA, nB, tA, tB;
        if (is64) {
            if (even) {
                longlong2 nv = *(const longlong2*)(p64 + e0);
                longlong2 tv = *(const longlong2*)(t64 + e0);
                nA = (int)nv.x; nB = (int)nv.y;
                tA = (int)tv.x; tB = (int)tv.y;
            } else {
                int eB = (e0 + 1 < n_edges) ? e0 + 1 : emax;
                nA = (int)__ldg(p64 + e0); nB = (int)__ldg(p64 + eB);
                tA = (int)__ldg(t64 + e0); tB = (int)__ldg(t64 + eB);
            }
        } else {
            if (even) {
                int2 nv = *(const int2*)(p32 + e0);
                int2 tv = *(const int2*)(t32 + e0);
                nA = nv.x; nB = nv.y;
                tA = tv.x; tB = tv.y;
            } else {
                int eB = (e0 + 1 < n_edges) ? e0 + 1 : emax;
                nA = __ldg(p32 + e0); nB = __ldg(p32 + eB);
                tA = __ldg(t32 + e0); tB = __ldg(t32 + eB);
            }
        }

        uint4 hv0 = *(const uint4*)(htab + nA * L1D + hq);
        uint4 hv1 = *(const uint4*)(htab + nB * L1D + hq);
        uint4 wv0 = *(const uint4*)(wch + tA * WROW + sub * 8);
        uint4 wv1 = *(const uint4*)(wch + tB * WROW + sub * 8);

        float acc0 = 0.f, acc1 = 0.f;
        const unsigned* hp0 = (const unsigned*)&hv0;
        const unsigned* wp0 = (const unsigned*)&wv0;
        const unsigned* hp1 = (const unsigned*)&hv1;
        const unsigned* wp1 = (const unsigned*)&wv1;
        #pragma unroll
        for (int k = 0; k < 4; k++) {
            float2 ha = __half22float2(*(const __half2*)(hp0 + k));
            float2 wa = __half22float2(*(const __half2*)(wp0 + k));
            acc0 = fmaf(ha.x, wa.x, acc0);
            acc0 = fmaf(ha.y, wa.y, acc0);
            float2 hb = __half22float2(*(const __half2*)(hp1 + k));
            float2 wb = __half22float2(*(const __half2*)(wp1 + k));
            acc1 = fmaf(hb.x, wb.x, acc1);
            acc1 = fmaf(hb.y, wb.y, acc1);
        }

        acc0 += __shfl_xor_sync(0xFFFFFFFFu, acc0, 1);
        acc1 += __shfl_xor_sync(0xFFFFFFFFu, acc1, 1);
        acc0 += __shfl_xor_sync(0xFFFFFFFFu, acc0, 2);
        acc1 += __shfl_xor_sync(0xFFFFFFFFu, acc1, 2);

        if (sub == 0) {
            float o0 = 1.f / (1.f + __expf(-acc0));
            float o1 = 1.f / (1.f + __expf(-acc1));
            if (e0 + 1 < n_edges) {
                *(float2*)(out + e0) = make_float2(o0, o1);
            } else {
                out[e0] = o0;
            }
        }
    }
}

// ---------------------------------------------------------------------------
// Launch. Inputs (metadata order): z, w1_l1, w1_l2, w2_l1, w2_l2,
// edge_index [2,E], edge_type [E].  Output: float32 [E].
// ---------------------------------------------------------------------------
extern "C" void kernel_launch(void* const* d_in, const int* in_sizes, int n_in,
                              void* d_out, int out_size) {
    const float* z     = (const float*)d_in[0];
    const float* w1_l1 = (const float*)d_in[1];
    const float* w1_l2 = (const float*)d_in[2];
    const float* w2_l1 = (const float*)d_in[3];
    const float* w2_l2 = (const float*)d_in[4];
    const void*  ei    = d_in[5];
    const void*  et    = d_in[6];
    float* out = (float*)d_out;

    int n_nodes = in_sizes[0] / IN_DIM;
    int n_etype = in_sizes[2] / L1D;
    int n_edges = out_size;

    int nb1 = (n_nodes + NPB1 - 1) / NPB1;
    node_mlp_kernel<<<nb1, 128>>>(z, w1_l1, w2_l1, n_nodes);

    size_t smem2 = (size_t)n_etype * WROW * sizeof(__half);
    edge_kernel<<<1184, 256, smem2>>>(w1_l2, w2_l2, ei, et, out, n_edges, n_etype);
}